// round 7
// baseline (speedup 1.0000x reference)
#include <cuda_runtime.h>
#include <cstdint>
#include <math.h>

#define N_BATCH 4096
#define D_FEAT  64
#define KDIM    256                       // packed [u, -2mu, a, b]
#define TILE    128
#define NBLK    (N_BATCH / TILE)          // 32
#define NPAIRS  (NBLK * (NBLK + 1) / 2)   // 528
#define NCHUNK  8                         // k chunks of 32
#define STAGES  3
#define NTHR    128                       // 4 warps, each 64x64 tile

// ---- scratch (static device globals; no allocation allowed) ----
// A-operand layout: [blk 32][chunk 8][rb 8][kb 4][lane 32][slot 4] floats
__device__ __align__(256) float g_VA[N_BATCH * KDIM];
// B-operand layout (k rotated by 128): [blk 32][chunk 8][nb 16][kb2 2][lane 32][slot 4]
// slot = (kb&1)*2 + quad  -> one LDS.128 carries two kk steps
__device__ __align__(256) float g_VB[N_BATCH * KDIM];
__device__ __align__(256) float g_C[N_BATCH];
__device__ __align__(256) float g_P[N_BATCH];
__device__ __align__(256) float g_RP[N_BATCH];
__device__ double g_acc[2];
__device__ unsigned g_done;

// ---- smem: 3 stages x 32KB (A 16KB + B 16KB); epilogue reuses stage 0 ----
#define STAGE_FLOATS 8192
#define SM_FLOATS   (STAGES * STAGE_FLOATS)
#define SM_BYTES    (SM_FLOATS * 4)
#define OFF_ROWD 0      // 128 float4
#define OFF_COLD 2048   // 128 float4
#define OFF_REDP 4096
#define OFF_REDN 4100

// ---------------------------------------------------------------
__device__ __forceinline__ uint32_t smem_u32(const void* p) {
    uint32_t a;
    asm("{ .reg .u64 t; cvta.to.shared.u64 t, %1; cvt.u32.u64 %0, t; }" : "=r"(a) : "l"(p));
    return a;
}
__device__ __forceinline__ void cp16(uint32_t dst, const void* src) {
    asm volatile("cp.async.cg.shared.global [%0], [%1], 16;" :: "r"(dst), "l"(src));
}
#define CP_COMMIT() asm volatile("cp.async.commit_group;" ::: "memory")
#define CP_WAIT(n)  asm volatile("cp.async.wait_group %0;" :: "n"(n) : "memory")

// ---------------------------------------------------------------
// 4096 blocks x 128 threads: tf32-round, write fragment-permuted operands
__global__ void precompute_kernel(const float* __restrict__ mu,
                                  const float* __restrict__ var) {
    int row = blockIdx.x;
    int tid = threadIdx.x;
    if (row == 0 && tid == 0) { g_acc[0] = 0.0; g_acc[1] = 0.0; }
    int d = tid & 63;
    float v  = var[row * D_FEAT + d];
    float m  = mu [row * D_FEAT + d];
    float iv = 1.0f / v;
    float x, y;
    if (tid < 64) { x = v + m * m;  y = iv; }      // k = tid, k = 128+tid
    else          { x = -2.0f * m;  y = m * iv; }
    uint32_t xr, yr;
    asm("cvt.rna.tf32.f32 %0, %1;" : "=r"(xr) : "f"(x));
    asm("cvt.rna.tf32.f32 %0, %1;" : "=r"(yr) : "f"(y));

    int b = row >> 7, r = row & 127;
    int rb = r >> 4, ri = r & 15;
    int nb = r >> 3, ji = r & 7;
    uint32_t* VA = (uint32_t*)g_VA;
    uint32_t* VB = (uint32_t*)g_VB;
    uint32_t vals[2] = { xr, yr };
    int ks[2] = { tid, 128 + tid };
    #pragma unroll
    for (int q = 0; q < 2; q++) {
        int k = ks[q];
        int c  = k >> 5, kc = k & 31, kb = kc >> 3, kw = kc & 7;
        int cB = (c + 4) & 7;   // J-side rotation baked into B layout
        int laneA = (ri & 7) * 4 + (kw & 3);
        int slotA = (ri >> 3) + 2 * (kw >> 2);
        size_t offA = ((((size_t)b * 8 + c) * 8 + rb) * 4 + kb) * 128 + laneA * 4 + slotA;
        VA[offA] = vals[q];
        int laneB = ji * 4 + (kw & 3);
        int slotB = (kb & 1) * 2 + (kw >> 2);
        size_t offB = ((((size_t)b * 8 + cB) * 16 + nb) * 2 + (kb >> 1)) * 128 + laneB * 4 + slotB;
        VB[offB] = vals[q];
    }

    __shared__ float sc[64];
    __shared__ float sp[64];
    if (tid < 64) { sc[tid] = m * m * iv; sp[tid] = v; }
    __syncthreads();
    #pragma unroll
    for (int s = 32; s > 0; s >>= 1) {
        if (tid < s) { sc[tid] += sc[tid + s]; sp[tid] *= sp[tid + s]; }
        __syncthreads();
    }
    if (tid == 0) {
        g_C[row]  = sc[0];
        g_P[row]  = sp[0];
        g_RP[row] = 1.0f / (sp[0] + 1e-8f);
    }
}

// ---------------------------------------------------------------
__device__ __forceinline__ void issue_chunk(uint32_t smbase, int stage,
                                            int bi, int bj, int c, int tid) {
    const float* srcA = g_VA + ((size_t)bi * 8 + c) * 4096;
    const float* srcB = g_VB + ((size_t)bj * 8 + c) * 4096;
    uint32_t dst = smbase + stage * (STAGE_FLOATS * 4);
    #pragma unroll
    for (int it = 0; it < 8; it++) {
        int idx = tid + it * NTHR;
        cp16(dst + idx * 16,         srcA + idx * 4);
        cp16(dst + 16384 + idx * 16, srcB + idx * 4);
    }
    CP_COMMIT();
}

// fragment loads
__device__ __forceinline__ void lda(const float* pA, int wm, int kk, int lane,
                                    uint32_t a[4][4]) {
    #pragma unroll
    for (int tm = 0; tm < 4; tm++) {
        const uint4 v = *(const uint4*)(pA + (((wm * 4 + tm) * 4 + kk) * 32 + lane) * 4);
        a[tm][0] = v.x; a[tm][1] = v.y; a[tm][2] = v.z; a[tm][3] = v.w;
    }
}
__device__ __forceinline__ void ldb8(const float* pB, int wn, int kb2, int lane,
                                     uint32_t b[8][4]) {
    #pragma unroll
    for (int tn = 0; tn < 8; tn++) {
        const uint4 v = *(const uint4*)(pB + (((wn * 8 + tn) * 2 + kb2) * 32 + lane) * 4);
        b[tn][0] = v.x; b[tn][1] = v.y; b[tn][2] = v.z; b[tn][3] = v.w;
    }
}

__device__ __forceinline__ void ep_elem(float S, float4 R, float4 C, int r, int cl,
                                        bool diag, float& pos, float& neg) {
    float sym = fmaf(0.25f, S, R.x) + fmaf(R.z, C.x, fmaf(R.y, C.y, C.z));
    float sig = __fdividef(1.0f, 1.0f + __expf(-sym));
    float w = (!diag || (r < cl)) ? 2.0f : 0.0f;
    float t = w * sig;
    if (__float_as_int(R.w) == __float_as_int(C.w)) pos += t; else neg += t;
}

extern __shared__ __align__(16) float sm_dyn[];

__global__ void __launch_bounds__(NTHR)
pair_kernel(const int* __restrict__ labels, float* __restrict__ out) {
    float* sm = sm_dyn;
    uint32_t smb = smem_u32(sm);
    int tid  = threadIdx.x;
    int wid  = tid >> 5;
    int lane = tid & 31;
    int wm = wid & 1;        // 64-row half
    int wn = wid >> 1;       // 64-col half

    int t = blockIdx.x, bi = 0;
    while (t >= NBLK - bi) { t -= NBLK - bi; bi++; }
    int bj = bi + t;

    float acc[4][8][4];
    #pragma unroll
    for (int i = 0; i < 4; i++)
        #pragma unroll
        for (int j = 0; j < 8; j++)
            #pragma unroll
            for (int k = 0; k < 4; k++) acc[i][j][k] = 0.0f;

    issue_chunk(smb, 0, bi, bj, 0, tid);
    issue_chunk(smb, 1, bi, bj, 1, tid);

    #pragma unroll
    for (int c = 0; c < NCHUNK; c++) {
        if (c == NCHUNK - 1) CP_WAIT(0); else CP_WAIT(1);
        __syncthreads();
        if (c < NCHUNK - 2)
            issue_chunk(smb, (c + 2) % STAGES, bi, bj, c + 2, tid);

        const float* pA = sm + (c % STAGES) * STAGE_FLOATS;
        const float* pB = pA + 4096;
        #pragma unroll
        for (int kb2 = 0; kb2 < 2; kb2++) {
            uint32_t B[8][4];
            ldb8(pB, wn, kb2, lane, B);
            #pragma unroll
            for (int h = 0; h < 2; h++) {
                int kk = kb2 * 2 + h;
                uint32_t A[4][4];
                lda(pA, wm, kk, lane, A);
                #pragma unroll
                for (int tm = 0; tm < 4; tm++)
                    #pragma unroll
                    for (int tn = 0; tn < 8; tn++)
                        asm volatile(
                            "mma.sync.aligned.m16n8k8.row.col.f32.tf32.tf32.f32 "
                            "{%0,%1,%2,%3},{%4,%5,%6,%7},{%8,%9},{%0,%1,%2,%3};"
                            : "+f"(acc[tm][tn][0]), "+f"(acc[tm][tn][1]),
                              "+f"(acc[tm][tn][2]), "+f"(acc[tm][tn][3])
                            : "r"(A[tm][0]), "r"(A[tm][1]), "r"(A[tm][2]), "r"(A[tm][3]),
                              "r"(B[tn][h * 2]), "r"(B[tn][h * 2 + 1]));
            }
        }
    }

    // ---- epilogue (reuses stage-0 smem) ----
    __syncthreads();
    float4* rowd = (float4*)(sm + OFF_ROWD);
    float4* cold = (float4*)(sm + OFF_COLD);
    {
        int gi = bi * TILE + tid, gj = bj * TILE + tid;
        rowd[tid] = make_float4(0.25f * g_C[gi], g_P[gi], g_RP[gi],
                                __int_as_float(labels[gi]));
        cold[tid] = make_float4(0.25f * g_P[gj], 0.25f * g_RP[gj],
                                0.25f * g_C[gj] - 32.0f, __int_as_float(labels[gj]));
    }
    __syncthreads();

    bool diag = (bi == bj);
    float pos = 0.0f, neg = 0.0f;
    int r0 = wm * 64 + (lane >> 2);
    int c0 = wn * 64 + 2 * (lane & 3);
    #pragma unroll
    for (int tm = 0; tm < 4; tm++) {
        int r1 = r0 + tm * 16, r2 = r1 + 8;
        float4 R1 = rowd[r1], R2 = rowd[r2];
        #pragma unroll
        for (int tn = 0; tn < 8; tn++) {
            int ca = c0 + tn * 8;
            float4 C1 = cold[ca], C2 = cold[ca + 1];
            ep_elem(acc[tm][tn][0], R1, C1, r1, ca,     diag, pos, neg);
            ep_elem(acc[tm][tn][1], R1, C2, r1, ca + 1, diag, pos, neg);
            ep_elem(acc[tm][tn][2], R2, C1, r2, ca,     diag, pos, neg);
            ep_elem(acc[tm][tn][3], R2, C2, r2, ca + 1, diag, pos, neg);
        }
    }

    #pragma unroll
    for (int off = 16; off; off >>= 1) {
        pos += __shfl_xor_sync(0xffffffffu, pos, off);
        neg += __shfl_xor_sync(0xffffffffu, neg, off);
    }
    float* redp = sm + OFF_REDP;
    float* redn = sm + OFF_REDN;
    if (lane == 0) { redp[wid] = pos; redn[wid] = neg; }
    __syncthreads();
    if (tid == 0) {
        float p = 0.0f, n = 0.0f;
        #pragma unroll
        for (int i = 0; i < 4; i++) { p += redp[i]; n += redn[i]; }
        atomicAdd(&g_acc[0], (double)p);
        atomicAdd(&g_acc[1], (double)n);
        __threadfence();
        unsigned v = atomicAdd(&g_done, 1u);
        if (v == NPAIRS - 1) {               // last CTA finalizes
            g_done = 0;
            double P = g_acc[0], N = g_acc[1];
            const double invN2 = 1.0 / ((double)N_BATCH * (double)N_BATCH);
            out[0] = (float)(P * invN2);
            out[1] = (float)(N * invN2);
            out[2] = (float)P;
            out[3] = (float)N;
        }
    }
}

// ---------------------------------------------------------------
extern "C" void kernel_launch(void* const* d_in, const int* in_sizes, int n_in,
                              void* d_out, int out_size) {
    const float* mu     = (const float*)d_in[0];
    const float* var    = (const float*)d_in[1];
    const int*   labels = (const int*)d_in[2];
    float* out = (float*)d_out;

    cudaFuncSetAttribute(pair_kernel, cudaFuncAttributeMaxDynamicSharedMemorySize, SM_BYTES);

    precompute_kernel<<<N_BATCH, 128>>>(mu, var);
    pair_kernel<<<NPAIRS, NTHR, SM_BYTES>>>(labels, out);
}

// round 8
// speedup vs baseline: 1.4653x; 1.4653x over previous
#include <cuda_runtime.h>
#include <cstdint>
#include <math.h>

#define N_BATCH 4096
#define D_FEAT  64
#define KDIM    256                       // packed [u, -2mu, a, b]
#define TILE    128
#define NBLK    (N_BATCH / TILE)          // 32
#define NPAIRS  (NBLK * (NBLK + 1) / 2)   // 528
#define NCHUNK  8                         // k chunks of 32
#define STAGES  3
#define NTHR    256

// ---- scratch (static device globals; no allocation allowed) ----
// A-operand layout: [blk 32][chunk 8][rb 8][kb 4][lane 32][slot 4] floats
__device__ __align__(256) float g_VA[N_BATCH * KDIM];
// B-operand layout (k rotated by 128): [blk 32][chunk 8][nb 16][kb2 2][lane 32][slot 4]
// slot = (kb&1)*2 + quad  -> one LDS.128 carries two kk steps
__device__ __align__(256) float g_VB[N_BATCH * KDIM];
__device__ __align__(256) float g_C[N_BATCH];
__device__ __align__(256) float g_P[N_BATCH];
__device__ __align__(256) float g_RP[N_BATCH];
__device__ double g_acc[2];
__device__ unsigned g_done;

// ---- smem: 3 stages x 32KB (A 16KB + B 16KB) + mbarriers; epilogue reuses stage 0 ----
#define STAGE_FLOATS 8192
#define MB_BASE   (STAGES * STAGE_FLOATS * 4)   // 98304 (bytes)
#define SM_BYTES  (MB_BASE + 64)
#define OFF_ROWD 0      // 128 float4
#define OFF_COLD 2048   // 128 float4
#define OFF_REDP 4096
#define OFF_REDN 4104

// ---------------------------------------------------------------
__device__ __forceinline__ uint32_t smem_u32(const void* p) {
    uint32_t a;
    asm("{ .reg .u64 t; cvta.to.shared.u64 t, %1; cvt.u32.u64 %0, t; }" : "=r"(a) : "l"(p));
    return a;
}
__device__ __forceinline__ void cp16(uint32_t dst, const void* src) {
    asm volatile("cp.async.cg.shared.global [%0], [%1], 16;" :: "r"(dst), "l"(src));
}
#define MB_INIT(mb, c)  asm volatile("mbarrier.init.shared.b64 [%0], %1;" :: "r"(mb), "r"((uint32_t)(c)) : "memory")
#define MB_ARRIVE(mb)   asm volatile("mbarrier.arrive.shared.b64 _, [%0];" :: "r"(mb) : "memory")
#define CP_MB_ARRIVE(mb) asm volatile("cp.async.mbarrier.arrive.noinc.shared.b64 [%0];" :: "r"(mb) : "memory")

__device__ __forceinline__ void mbwait(uint32_t mb, uint32_t phase) {
    asm volatile(
        "{\n\t.reg .pred P;\n\t"
        "LW_%=:\n\t"
        "mbarrier.try_wait.parity.shared.b64 P, [%0], %1;\n\t"
        "@!P bra LW_%=;\n\t}"
        :: "r"(mb), "r"(phase) : "memory");
}
__device__ __forceinline__ uint32_t mb_full(uint32_t smb, int s)  { return smb + MB_BASE + s * 16; }
__device__ __forceinline__ uint32_t mb_empty(uint32_t smb, int s) { return smb + MB_BASE + s * 16 + 8; }

// ---------------------------------------------------------------
// 4096 blocks x 128 threads: tf32-round, write fragment-permuted operands
__global__ void precompute_kernel(const float* __restrict__ mu,
                                  const float* __restrict__ var) {
    int row = blockIdx.x;
    int tid = threadIdx.x;
    if (row == 0 && tid == 0) { g_acc[0] = 0.0; g_acc[1] = 0.0; }
    int d = tid & 63;
    float v  = var[row * D_FEAT + d];
    float m  = mu [row * D_FEAT + d];
    float iv = 1.0f / v;
    float x, y;
    if (tid < 64) { x = v + m * m;  y = iv; }      // k = tid, k = 128+tid
    else          { x = -2.0f * m;  y = m * iv; }
    uint32_t xr, yr;
    asm("cvt.rna.tf32.f32 %0, %1;" : "=r"(xr) : "f"(x));
    asm("cvt.rna.tf32.f32 %0, %1;" : "=r"(yr) : "f"(y));

    int b = row >> 7, r = row & 127;
    int rb = r >> 4, ri = r & 15;
    int nb = r >> 3, ji = r & 7;
    uint32_t* VA = (uint32_t*)g_VA;
    uint32_t* VB = (uint32_t*)g_VB;
    uint32_t vals[2] = { xr, yr };
    int ks[2] = { tid, 128 + tid };
    #pragma unroll
    for (int q = 0; q < 2; q++) {
        int k = ks[q];
        int c  = k >> 5, kc = k & 31, kb = kc >> 3, kw = kc & 7;
        int cB = (c + 4) & 7;   // J-side rotation baked into B layout
        int laneA = (ri & 7) * 4 + (kw & 3);
        int slotA = (ri >> 3) + 2 * (kw >> 2);
        size_t offA = ((((size_t)b * 8 + c) * 8 + rb) * 4 + kb) * 128 + laneA * 4 + slotA;
        VA[offA] = vals[q];
        int laneB = ji * 4 + (kw & 3);
        int slotB = (kb & 1) * 2 + (kw >> 2);
        size_t offB = ((((size_t)b * 8 + cB) * 16 + nb) * 2 + (kb >> 1)) * 128 + laneB * 4 + slotB;
        VB[offB] = vals[q];
    }

    __shared__ float sc[64];
    __shared__ float sp[64];
    if (tid < 64) { sc[tid] = m * m * iv; sp[tid] = v; }
    __syncthreads();
    #pragma unroll
    for (int s = 32; s > 0; s >>= 1) {
        if (tid < s) { sc[tid] += sc[tid + s]; sp[tid] *= sp[tid + s]; }
        __syncthreads();
    }
    if (tid == 0) {
        g_C[row]  = sc[0];
        g_P[row]  = sp[0];
        g_RP[row] = 1.0f / (sp[0] + 1e-8f);
    }
}

// ---------------------------------------------------------------
__device__ __forceinline__ void issue_chunk(uint32_t smbase, int stage,
                                            int bi, int bj, int c, int tid) {
    const float* srcA = g_VA + ((size_t)bi * 8 + c) * 4096;
    const float* srcB = g_VB + ((size_t)bj * 8 + c) * 4096;
    uint32_t dst = smbase + stage * (STAGE_FLOATS * 4);
    #pragma unroll
    for (int it = 0; it < 4; it++) {
        int idx = tid + it * NTHR;
        cp16(dst + idx * 16,         srcA + idx * 4);
        cp16(dst + 16384 + idx * 16, srcB + idx * 4);
    }
}

// fragment loads
__device__ __forceinline__ void lda(const float* pA, int wm, int kk, int lane,
                                    uint32_t a[4][4]) {
    #pragma unroll
    for (int tm = 0; tm < 4; tm++) {
        const uint4 v = *(const uint4*)(pA + (((wm * 4 + tm) * 4 + kk) * 32 + lane) * 4);
        a[tm][0] = v.x; a[tm][1] = v.y; a[tm][2] = v.z; a[tm][3] = v.w;
    }
}
__device__ __forceinline__ void ldb4(const float* pB, int wn, int kb2, int lane,
                                     uint32_t b[4][4]) {
    #pragma unroll
    for (int tn = 0; tn < 4; tn++) {
        const uint4 v = *(const uint4*)(pB + (((wn * 4 + tn) * 2 + kb2) * 32 + lane) * 4);
        b[tn][0] = v.x; b[tn][1] = v.y; b[tn][2] = v.z; b[tn][3] = v.w;
    }
}

__device__ __forceinline__ void ep_elem(float S, float4 R, float4 C, int r, int cl,
                                        bool diag, float& pos, float& neg) {
    float sym = fmaf(0.25f, S, R.x) + fmaf(R.z, C.x, fmaf(R.y, C.y, C.z));
    float sig = __fdividef(1.0f, 1.0f + __expf(-sym));
    float w = (!diag || (r < cl)) ? 2.0f : 0.0f;
    float t = w * sig;
    if (__float_as_int(R.w) == __float_as_int(C.w)) pos += t; else neg += t;
}

extern __shared__ __align__(16) float sm_dyn[];

__global__ void __launch_bounds__(NTHR, 2)
pair_kernel(const int* __restrict__ labels, float* __restrict__ out) {
    float* sm = sm_dyn;
    uint32_t smb = smem_u32(sm);
    int tid  = threadIdx.x;
    int wid  = tid >> 5;
    int lane = tid & 31;
    int wm = wid & 1;        // 64-row half
    int wn = wid >> 1;       // 32-col quarter

    int t = blockIdx.x, bi = 0;
    while (t >= NBLK - bi) { t -= NBLK - bi; bi++; }
    int bj = bi + t;

    float acc[4][4][4];
    #pragma unroll
    for (int i = 0; i < 4; i++)
        #pragma unroll
        for (int j = 0; j < 4; j++)
            #pragma unroll
            for (int k = 0; k < 4; k++) acc[i][j][k] = 0.0f;

    // ---- init mbarriers ----
    if (tid == 0) {
        #pragma unroll
        for (int s = 0; s < STAGES; s++) {
            MB_INIT(mb_full(smb, s), NTHR);
            MB_INIT(mb_empty(smb, s), NTHR);
        }
    }
    __syncthreads();

    // prologue: issue chunks 0 and 1
    issue_chunk(smb, 0, bi, bj, 0, tid);
    CP_MB_ARRIVE(mb_full(smb, 0));
    issue_chunk(smb, 1, bi, bj, 1, tid);
    CP_MB_ARRIVE(mb_full(smb, 1));

    #pragma unroll
    for (int c = 0; c < NCHUNK; c++) {
        const int s = c % STAGES;
        // producer for chunk c+2 (stage reuse gated by empty barrier)
        if (c + 2 < NCHUNK) {
            const int c2 = c + 2, s2 = c2 % STAGES, k2 = c2 / STAGES;
            if (k2 > 0) mbwait(mb_empty(smb, s2), (uint32_t)((k2 - 1) & 1));
            issue_chunk(smb, s2, bi, bj, c2, tid);
            CP_MB_ARRIVE(mb_full(smb, s2));
        }
        // consumer
        mbwait(mb_full(smb, s), (uint32_t)((c / STAGES) & 1));

        const float* pA = sm + s * STAGE_FLOATS;
        const float* pB = pA + 4096;
        #pragma unroll
        for (int kb2 = 0; kb2 < 2; kb2++) {
            uint32_t B[4][4];
            ldb4(pB, wn, kb2, lane, B);
            #pragma unroll
            for (int h = 0; h < 2; h++) {
                int kk = kb2 * 2 + h;
                uint32_t A[4][4];
                lda(pA, wm, kk, lane, A);
                #pragma unroll
                for (int tm = 0; tm < 4; tm++)
                    #pragma unroll
                    for (int tn = 0; tn < 4; tn++)
                        asm volatile(
                            "mma.sync.aligned.m16n8k8.row.col.f32.tf32.tf32.f32 "
                            "{%0,%1,%2,%3},{%4,%5,%6,%7},{%8,%9},{%0,%1,%2,%3};"
                            : "+f"(acc[tm][tn][0]), "+f"(acc[tm][tn][1]),
                              "+f"(acc[tm][tn][2]), "+f"(acc[tm][tn][3])
                            : "r"(A[tm][0]), "r"(A[tm][1]), "r"(A[tm][2]), "r"(A[tm][3]),
                              "r"(B[tn][h * 2]), "r"(B[tn][h * 2 + 1]));
            }
        }
        // release this stage (MMA issue order guarantees LDS data landed)
        MB_ARRIVE(mb_empty(smb, s));
    }

    // ---- epilogue (reuses stage-0 smem after full-block sync) ----
    __syncthreads();
    float4* rowd = (float4*)(sm + OFF_ROWD);
    float4* cold = (float4*)(sm + OFF_COLD);
    if (tid < 128) {
        int gi = bi * TILE + tid, gj = bj * TILE + tid;
        rowd[tid] = make_float4(0.25f * g_C[gi], g_P[gi], g_RP[gi],
                                __int_as_float(labels[gi]));
        cold[tid] = make_float4(0.25f * g_P[gj], 0.25f * g_RP[gj],
                                0.25f * g_C[gj] - 32.0f, __int_as_float(labels[gj]));
    }
    __syncthreads();

    bool diag = (bi == bj);
    float pos = 0.0f, neg = 0.0f;
    int r0 = wm * 64 + (lane >> 2);
    int c0 = wn * 32 + 2 * (lane & 3);
    #pragma unroll
    for (int tm = 0; tm < 4; tm++) {
        int r1 = r0 + tm * 16, r2 = r1 + 8;
        float4 R1 = rowd[r1], R2 = rowd[r2];
        #pragma unroll
        for (int tn = 0; tn < 4; tn++) {
            int ca = c0 + tn * 8;
            float4 C1 = cold[ca], C2 = cold[ca + 1];
            ep_elem(acc[tm][tn][0], R1, C1, r1, ca,     diag, pos, neg);
            ep_elem(acc[tm][tn][1], R1, C2, r1, ca + 1, diag, pos, neg);
            ep_elem(acc[tm][tn][2], R2, C1, r2, ca,     diag, pos, neg);
            ep_elem(acc[tm][tn][3], R2, C2, r2, ca + 1, diag, pos, neg);
        }
    }

    #pragma unroll
    for (int off = 16; off; off >>= 1) {
        pos += __shfl_xor_sync(0xffffffffu, pos, off);
        neg += __shfl_xor_sync(0xffffffffu, neg, off);
    }
    float* redp = sm + OFF_REDP;
    float* redn = sm + OFF_REDN;
    if (lane == 0) { redp[wid] = pos; redn[wid] = neg; }
    __syncthreads();
    if (tid == 0) {
        float p = 0.0f, n = 0.0f;
        #pragma unroll
        for (int i = 0; i < 8; i++) { p += redp[i]; n += redn[i]; }
        atomicAdd(&g_acc[0], (double)p);
        atomicAdd(&g_acc[1], (double)n);
        __threadfence();
        unsigned v = atomicAdd(&g_done, 1u);
        if (v == NPAIRS - 1) {               // last CTA finalizes
            g_done = 0;
            double P = g_acc[0], N = g_acc[1];
            const double invN2 = 1.0 / ((double)N_BATCH * (double)N_BATCH);
            out[0] = (float)(P * invN2);
            out[1] = (float)(N * invN2);
            out[2] = (float)P;
            out[3] = (float)N;
        }
    }
}

// ---------------------------------------------------------------
extern "C" void kernel_launch(void* const* d_in, const int* in_sizes, int n_in,
                              void* d_out, int out_size) {
    const float* mu     = (const float*)d_in[0];
    const float* var    = (const float*)d_in[1];
    const int*   labels = (const int*)d_in[2];
    float* out = (float*)d_out;

    cudaFuncSetAttribute(pair_kernel, cudaFuncAttributeMaxDynamicSharedMemorySize, SM_BYTES);

    precompute_kernel<<<N_BATCH, 128>>>(mu, var);
    pair_kernel<<<NPAIRS, NTHR, SM_BYTES>>>(labels, out);
}

// round 9
// speedup vs baseline: 1.9511x; 1.3315x over previous
#include <cuda_runtime.h>
#include <cuda_bf16.h>
#include <cstdint>
#include <math.h>

#define N_BATCH 4096
#define D_FEAT  64
#define KDIM    256                       // packed [u, -2mu, a, b]
#define TILE    128
#define NBLK    (N_BATCH / TILE)          // 32
#define NPAIRS  (NBLK * (NBLK + 1) / 2)   // 528
#define NCHUNK  8                         // k chunks of 32
#define STAGES  3
#define NTHR    256

// ---- scratch (static device globals; no allocation allowed) ----
// bf16 fragment-permuted operands for mma.sync.m16n8k16
// A: [blk 32][chunk 8][rb 8][ks 2][lane 32][slot 4][half 2] bf16
__device__ __align__(256) __nv_bfloat16 g_VA[N_BATCH * KDIM];
// B (k rotated by 128): [blk 32][chunk 8][nb 16][lane 32][slot 4][half 2] bf16
//   slot = ks*2 + reg  -> one LDS.128 carries both ksteps of a B fragment
__device__ __align__(256) __nv_bfloat16 g_VB[N_BATCH * KDIM];
__device__ __align__(256) float g_C[N_BATCH];
__device__ __align__(256) float g_P[N_BATCH];
__device__ __align__(256) float g_RP[N_BATCH];
__device__ double g_acc[2];
__device__ unsigned g_done;

// ---- smem: 3 stages x 16KB (A 8KB + B 8KB) + mbarriers; epilogue reuses stage 0 ----
#define STAGE_BYTES 16384
#define MB_BASE   (STAGES * STAGE_BYTES)   // 49152
#define SM_BYTES  (MB_BASE + 64)
#define OFF_ROWD 0      // 128 float4 (bytes 0..2048)
#define OFF_COLD 2048
#define OFF_REDP 4096
#define OFF_REDN 4136

// ---------------------------------------------------------------
__device__ __forceinline__ uint32_t smem_u32(const void* p) {
    uint32_t a;
    asm("{ .reg .u64 t; cvta.to.shared.u64 t, %1; cvt.u32.u64 %0, t; }" : "=r"(a) : "l"(p));
    return a;
}
__device__ __forceinline__ void cp16(uint32_t dst, const void* src) {
    asm volatile("cp.async.cg.shared.global [%0], [%1], 16;" :: "r"(dst), "l"(src));
}
#define MB_INIT(mb, c)  asm volatile("mbarrier.init.shared.b64 [%0], %1;" :: "r"(mb), "r"((uint32_t)(c)) : "memory")
#define MB_ARRIVE(mb)   asm volatile("mbarrier.arrive.shared.b64 _, [%0];" :: "r"(mb) : "memory")
#define CP_MB_ARRIVE(mb) asm volatile("cp.async.mbarrier.arrive.noinc.shared.b64 [%0];" :: "r"(mb) : "memory")

__device__ __forceinline__ void mbwait(uint32_t mb, uint32_t phase) {
    asm volatile(
        "{\n\t.reg .pred P;\n\t"
        "LW_%=:\n\t"
        "mbarrier.try_wait.parity.shared.b64 P, [%0], %1;\n\t"
        "@!P bra LW_%=;\n\t}"
        :: "r"(mb), "r"(phase) : "memory");
}
__device__ __forceinline__ uint32_t mb_full(uint32_t smb, int s)  { return smb + MB_BASE + s * 16; }
__device__ __forceinline__ uint32_t mb_empty(uint32_t smb, int s) { return smb + MB_BASE + s * 16 + 8; }

// ---------------------------------------------------------------
// 4096 blocks x 128 threads: bf16-round, write fragment-permuted operands
__global__ void precompute_kernel(const float* __restrict__ mu,
                                  const float* __restrict__ var) {
    int row = blockIdx.x;
    int tid = threadIdx.x;
    if (row == 0 && tid == 0) { g_acc[0] = 0.0; g_acc[1] = 0.0; }
    int d = tid & 63;
    float v  = var[row * D_FEAT + d];
    float m  = mu [row * D_FEAT + d];
    float iv = 1.0f / v;
    float x, y;
    if (tid < 64) { x = v + m * m;  y = iv; }      // k = tid, k = 128+tid
    else          { x = -2.0f * m;  y = m * iv; }
    __nv_bfloat16 vals[2] = { __float2bfloat16_rn(x), __float2bfloat16_rn(y) };

    int b = row >> 7, r = row & 127;
    int rb = r >> 4, ri = r & 15;
    int nb = r >> 3, ji = r & 7;
    int ks_[2] = { tid, 128 + tid };
    #pragma unroll
    for (int q = 0; q < 2; q++) {
        int k = ks_[q];
        int c  = k >> 5, kc = k & 31;
        int ks = kc >> 4, kk = kc & 15;
        int half = kk & 1;
        int cB = (c + 4) & 7;   // J-side rotation baked into B layout
        // A-side: lane=(ri&7)*4 + (kk>>1)&3 ; slot=(ri>>3) + 2*(kk>>3)
        int laneA = (ri & 7) * 4 + ((kk >> 1) & 3);
        int slotA = (ri >> 3) + 2 * (kk >> 3);
        size_t offA = (((((size_t)b * 8 + c) * 8 + rb) * 2 + ks) * 32 + laneA) * 8 + slotA * 2 + half;
        g_VA[offA] = vals[q];
        // B-side: lane=ji*4 + (kk>>1)&3 ; slot=ks*2 + (kk>>3)
        int laneB = ji * 4 + ((kk >> 1) & 3);
        int slotB = ks * 2 + (kk >> 3);
        size_t offB = ((((size_t)b * 8 + cB) * 16 + nb) * 32 + laneB) * 8 + slotB * 2 + half;
        g_VB[offB] = vals[q];
    }

    __shared__ float sc[64];
    __shared__ float sp[64];
    if (tid < 64) { sc[tid] = m * m * iv; sp[tid] = v; }
    __syncthreads();
    #pragma unroll
    for (int s = 32; s > 0; s >>= 1) {
        if (tid < s) { sc[tid] += sc[tid + s]; sp[tid] *= sp[tid + s]; }
        __syncthreads();
    }
    if (tid == 0) {
        g_C[row]  = sc[0];
        g_P[row]  = sp[0];
        g_RP[row] = 1.0f / (sp[0] + 1e-8f);
    }
}

// ---------------------------------------------------------------
// One chunk = 16KB: A 8KB + B 8KB. 256 threads x 4 cp16 = 16KB.
__device__ __forceinline__ void issue_chunk(uint32_t smbase, int stage,
                                            int bi, int bj, int c, int tid) {
    const __nv_bfloat16* srcA = g_VA + ((size_t)bi * 8 + c) * 4096;
    const __nv_bfloat16* srcB = g_VB + ((size_t)bj * 8 + c) * 4096;
    uint32_t dst = smbase + stage * STAGE_BYTES;
    #pragma unroll
    for (int it = 0; it < 2; it++) {
        int idx = tid + it * NTHR;
        cp16(dst + idx * 16,        srcA + idx * 8);
        cp16(dst + 8192 + idx * 16, srcB + idx * 8);
    }
}

// fragment loads (uint4 units within a stage)
__device__ __forceinline__ void lda(const uint4* pA, int wm, int ks, int lane,
                                    uint32_t a[4][4]) {
    #pragma unroll
    for (int tm = 0; tm < 4; tm++) {
        const uint4 v = pA[(((wm * 4 + tm) * 2 + ks) * 32 + lane)];
        a[tm][0] = v.x; a[tm][1] = v.y; a[tm][2] = v.z; a[tm][3] = v.w;
    }
}
__device__ __forceinline__ void ldb4(const uint4* pB, int wn, int lane,
                                     uint32_t b[4][4]) {
    #pragma unroll
    for (int tn = 0; tn < 4; tn++) {
        const uint4 v = pB[((wn * 4 + tn) * 32 + lane)];
        b[tn][0] = v.x; b[tn][1] = v.y; b[tn][2] = v.z; b[tn][3] = v.w;
    }
}

__device__ __forceinline__ void ep_elem(float S, float4 R, float4 C, int r, int cl,
                                        bool diag, float& pos, float& neg) {
    float sym = fmaf(0.25f, S, R.x) + fmaf(R.z, C.x, fmaf(R.y, C.y, C.z));
    float sig = __fdividef(1.0f, 1.0f + __expf(-sym));
    float w = (!diag || (r < cl)) ? 2.0f : 0.0f;
    float t = w * sig;
    if (__float_as_int(R.w) == __float_as_int(C.w)) pos += t; else neg += t;
}

extern __shared__ __align__(16) float sm_dyn[];

__global__ void __launch_bounds__(NTHR, 2)
pair_kernel(const int* __restrict__ labels, float* __restrict__ out) {
    float* sm = sm_dyn;
    uint32_t smb = smem_u32(sm);
    int tid  = threadIdx.x;
    int wid  = tid >> 5;
    int lane = tid & 31;
    int wm = wid & 1;        // 64-row half
    int wn = wid >> 1;       // 32-col quarter

    int t = blockIdx.x, bi = 0;
    while (t >= NBLK - bi) { t -= NBLK - bi; bi++; }
    int bj = bi + t;

    float acc[4][4][4];
    #pragma unroll
    for (int i = 0; i < 4; i++)
        #pragma unroll
        for (int j = 0; j < 4; j++)
            #pragma unroll
            for (int k = 0; k < 4; k++) acc[i][j][k] = 0.0f;

    // ---- init mbarriers ----
    if (tid == 0) {
        #pragma unroll
        for (int s = 0; s < STAGES; s++) {
            MB_INIT(mb_full(smb, s), NTHR);
            MB_INIT(mb_empty(smb, s), NTHR);
        }
    }
    __syncthreads();

    // prologue: issue chunks 0 and 1
    issue_chunk(smb, 0, bi, bj, 0, tid);
    CP_MB_ARRIVE(mb_full(smb, 0));
    issue_chunk(smb, 1, bi, bj, 1, tid);
    CP_MB_ARRIVE(mb_full(smb, 1));

    #pragma unroll
    for (int c = 0; c < NCHUNK; c++) {
        const int s = c % STAGES;
        if (c + 2 < NCHUNK) {
            const int c2 = c + 2, s2 = c2 % STAGES, k2 = c2 / STAGES;
            if (k2 > 0) mbwait(mb_empty(smb, s2), (uint32_t)((k2 - 1) & 1));
            issue_chunk(smb, s2, bi, bj, c2, tid);
            CP_MB_ARRIVE(mb_full(smb, s2));
        }
        mbwait(mb_full(smb, s), (uint32_t)((c / STAGES) & 1));

        const uint4* pA = (const uint4*)((const char*)sm + s * STAGE_BYTES);
        const uint4* pB = (const uint4*)((const char*)sm + s * STAGE_BYTES + 8192);
        uint32_t B[4][4];
        ldb4(pB, wn, lane, B);
        #pragma unroll
        for (int ks = 0; ks < 2; ks++) {
            uint32_t A[4][4];
            lda(pA, wm, ks, lane, A);
            #pragma unroll
            for (int tm = 0; tm < 4; tm++)
                #pragma unroll
                for (int tn = 0; tn < 4; tn++)
                    asm volatile(
                        "mma.sync.aligned.m16n8k16.row.col.f32.bf16.bf16.f32 "
                        "{%0,%1,%2,%3},{%4,%5,%6,%7},{%8,%9},{%0,%1,%2,%3};"
                        : "+f"(acc[tm][tn][0]), "+f"(acc[tm][tn][1]),
                          "+f"(acc[tm][tn][2]), "+f"(acc[tm][tn][3])
                        : "r"(A[tm][0]), "r"(A[tm][1]), "r"(A[tm][2]), "r"(A[tm][3]),
                          "r"(B[tn][ks * 2]), "r"(B[tn][ks * 2 + 1]));
        }
        MB_ARRIVE(mb_empty(smb, s));
    }

    // ---- epilogue (reuses stage-0 smem after full-block sync) ----
    __syncthreads();
    float4* rowd = (float4*)((char*)sm + OFF_ROWD);
    float4* cold = (float4*)((char*)sm + OFF_COLD);
    if (tid < 128) {
        int gi = bi * TILE + tid, gj = bj * TILE + tid;
        rowd[tid] = make_float4(0.25f * g_C[gi], g_P[gi], g_RP[gi],
                                __int_as_float(labels[gi]));
        cold[tid] = make_float4(0.25f * g_P[gj], 0.25f * g_RP[gj],
                                0.25f * g_C[gj] - 32.0f, __int_as_float(labels[gj]));
    }
    __syncthreads();

    bool diag = (bi == bj);
    float pos = 0.0f, neg = 0.0f;
    int r0 = wm * 64 + (lane >> 2);
    int c0 = wn * 32 + 2 * (lane & 3);
    #pragma unroll
    for (int tm = 0; tm < 4; tm++) {
        int r1 = r0 + tm * 16, r2 = r1 + 8;
        float4 R1 = rowd[r1], R2 = rowd[r2];
        #pragma unroll
        for (int tn = 0; tn < 4; tn++) {
            int ca = c0 + tn * 8;
            float4 C1 = cold[ca], C2 = cold[ca + 1];
            ep_elem(acc[tm][tn][0], R1, C1, r1, ca,     diag, pos, neg);
            ep_elem(acc[tm][tn][1], R1, C2, r1, ca + 1, diag, pos, neg);
            ep_elem(acc[tm][tn][2], R2, C1, r2, ca,     diag, pos, neg);
            ep_elem(acc[tm][tn][3], R2, C2, r2, ca + 1, diag, pos, neg);
        }
    }

    #pragma unroll
    for (int off = 16; off; off >>= 1) {
        pos += __shfl_xor_sync(0xffffffffu, pos, off);
        neg += __shfl_xor_sync(0xffffffffu, neg, off);
    }
    float* redp = (float*)((char*)sm + OFF_REDP);
    float* redn = (float*)((char*)sm + OFF_REDN);
    if (lane == 0) { redp[wid] = pos; redn[wid] = neg; }
    __syncthreads();
    if (tid == 0) {
        float p = 0.0f, n = 0.0f;
        #pragma unroll
        for (int i = 0; i < 8; i++) { p += redp[i]; n += redn[i]; }
        atomicAdd(&g_acc[0], (double)p);
        atomicAdd(&g_acc[1], (double)n);
        __threadfence();
        unsigned v = atomicAdd(&g_done, 1u);
        if (v == NPAIRS - 1) {               // last CTA finalizes
            g_done = 0;
            double P = g_acc[0], N = g_acc[1];
            const double invN2 = 1.0 / ((double)N_BATCH * (double)N_BATCH);
            out[0] = (float)(P * invN2);
            out[1] = (float)(N * invN2);
            out[2] = (float)P;
            out[3] = (float)N;
        }
    }
}

// ---------------------------------------------------------------
extern "C" void kernel_launch(void* const* d_in, const int* in_sizes, int n_in,
                              void* d_out, int out_size) {
    const float* mu     = (const float*)d_in[0];
    const float* var    = (const float*)d_in[1];
    const int*   labels = (const int*)d_in[2];
    float* out = (float*)d_out;

    cudaFuncSetAttribute(pair_kernel, cudaFuncAttributeMaxDynamicSharedMemorySize, SM_BYTES);

    precompute_kernel<<<N_BATCH, 128>>>(mu, var);
    pair_kernel<<<NPAIRS, NTHR, SM_BYTES>>>(labels, out);
}